// round 1
// baseline (speedup 1.0000x reference)
#include <cuda_runtime.h>
#include <math.h>

#define NB   2048   // batch
#define NH   512    // hidden
#define N4H  2048   // 4*hidden
#define NA   8      // act (output) dim
#define NZ   64     // z dim
#define NT   64     // seq_len
#define MR   16     // batch rows per CTA
#define TPB  256

// Scratch for the time-invariant input projection (B, 4H) fp32 = 16 MB
__device__ float g_xproj[NB * N4H];

// ---------------------------------------------------------------------------
// Kernel 1: x_proj[b, j] = sum_k z[b,k] * W_ih[j, 8+k] + b_ih[j] + b_hh[j]
// (dec_in = [zeros(B,8), z] -> first 8 columns of W_ih never contribute)
// Each block: 256 j-columns x 16 batch rows, W row cached in registers.
// ---------------------------------------------------------------------------
__global__ __launch_bounds__(256, 1)
void xproj_kernel(const float* __restrict__ z, const float* __restrict__ Wih,
                  const float* __restrict__ bih, const float* __restrict__ bhh)
{
    const int j  = blockIdx.x * 256 + threadIdx.x;
    const int b0 = blockIdx.y * 16;
    __shared__ float zs[16][64];
    for (int i = threadIdx.x; i < 16 * 64; i += 256)
        zs[i >> 6][i & 63] = z[(b0 + (i >> 6)) * NZ + (i & 63)];
    __syncthreads();

    float w[64];
#pragma unroll
    for (int k4 = 0; k4 < 16; k4++) {
        // (j*72 + 8)*4 bytes is 16B-aligned: 288*j + 32, 288 % 16 == 0
        float4 v = *(const float4*)&Wih[j * (NA + NZ) + NA + k4 * 4];
        w[k4*4+0] = v.x; w[k4*4+1] = v.y; w[k4*4+2] = v.z; w[k4*4+3] = v.w;
    }
    const float bias = bih[j] + bhh[j];
#pragma unroll
    for (int bb = 0; bb < 16; bb++) {
        float acc = bias;
#pragma unroll
        for (int k = 0; k < 64; k++) acc += zs[bb][k] * w[k];
        g_xproj[(b0 + bb) * N4H + j] = acc;
    }
}

__device__ __forceinline__ float sigf(float x) { return 1.0f / (1.0f + expf(-x)); }

// ---------------------------------------------------------------------------
// Kernel 2: the full 64-step LSTM + output projection.
// Grid: 128 CTAs, each owns 16 batch rows for all timesteps (rows of the
// recurrence are independent -> zero inter-CTA communication).
//
// Per step, per gate chunk (order i, g, f, o so state fits in registers):
//   gates[16 x 512] = x_proj + h[16 x 512] @ W_hh_chunk.T[512 x 512]
// W_hh tiles (16 k x 512 n) are LDG->reg-transpose->STS double-buffered.
// Thread (tm, tn): rows 4*tm..+3, cols {tn*4..+3} u {256+tn*4..+3}
// (split column pairs keep every LDS.128 / STS.128 bank-conflict-free).
// ---------------------------------------------------------------------------
__global__ __launch_bounds__(TPB, 1)
void lstm_kernel(const float* __restrict__ Whh, const float* __restrict__ Wout,
                 const float* __restrict__ bout, float* __restrict__ out)
{
    extern __shared__ float smem[];
    float* h_sh    = smem;                  // 16*512           = 8192 floats
    float* wtb     = smem + MR * NH;        // 2 * 16*512       = 16384 floats
    float* wout_sh = wtb + 2 * 16 * NH;     // 8 * 516 (padded) = 4128 floats

    const int tid   = threadIdx.x;
    const int tn    = tid & 63;
    const int tm    = tid >> 6;
    const int r0    = tm << 2;
    const int brow0 = blockIdx.x * MR;

    // init state + W_out staging
    for (int i = tid; i < MR * NH; i += TPB) h_sh[i] = 0.0f;
    for (int i = tid; i < NA * NH; i += TPB) wout_sh[(i >> 9) * 516 + (i & 511)] = Wout[i];
    float bo = 0.0f;
    const int om = tid >> 3, oa = tid & 7;
    if (tid < 128) bo = bout[oa];
    __syncthreads();

    // W_hh staging task decode: 512 (n4,k4) tasks over 2 passes x 256 threads.
    // n4 = lane&7 fastest -> conflict-free STS.128 after in-register 4x4 transpose.
    int n4_[2], k4_[2];
#pragma unroll
    for (int p = 0; p < 2; p++) {
        int idx = p * TPB + tid;
        n4_[p] = (idx & 7) + ((idx >> 5) << 3);
        k4_[p] = (idx >> 3) & 3;
    }

    float cst[4][8], ig[4][8];
#pragma unroll
    for (int r = 0; r < 4; r++)
#pragma unroll
        for (int jj = 0; jj < 8; jj++) { cst[r][jj] = 0.0f; ig[r][jj] = 0.0f; }

    float4 pre[2][4];  // LDG prefetch registers (next tile)

#define LDG_TILE(chunk, kt) { \
  _Pragma("unroll") \
  for (int p = 0; p < 2; p++) { \
    const float* gp = Whh + (((chunk) * 512 + n4_[p] * 4) * NH + (kt) * 16 + k4_[p] * 4); \
    _Pragma("unroll") \
    for (int r = 0; r < 4; r++) pre[p][r] = *(const float4*)(gp + r * NH); \
  } }

#define STS_TILE(buf) { \
  _Pragma("unroll") \
  for (int p = 0; p < 2; p++) { \
    float* sp = wtb + (buf) * (16 * NH) + (k4_[p] * 4) * NH + n4_[p] * 4; \
    *(float4*)(sp)        = make_float4(pre[p][0].x, pre[p][1].x, pre[p][2].x, pre[p][3].x); \
    *(float4*)(sp + NH)   = make_float4(pre[p][0].y, pre[p][1].y, pre[p][2].y, pre[p][3].y); \
    *(float4*)(sp + 2*NH) = make_float4(pre[p][0].z, pre[p][1].z, pre[p][2].z, pre[p][3].z); \
    *(float4*)(sp + 3*NH) = make_float4(pre[p][0].w, pre[p][1].w, pre[p][2].w, pre[p][3].w); \
  } }

#define COMP_TILE(buf, kt) { \
  const float* wbase = wtb + (buf) * (16 * NH); \
  _Pragma("unroll") \
  for (int k4i = 0; k4i < 4; k4i++) { \
    float hb[4][4]; \
    _Pragma("unroll") \
    for (int r = 0; r < 4; r++) { \
      float4 q = *(const float4*)&h_sh[(r0 + r) * NH + (kt) * 16 + k4i * 4]; \
      hb[r][0] = q.x; hb[r][1] = q.y; hb[r][2] = q.z; hb[r][3] = q.w; \
    } \
    _Pragma("unroll") \
    for (int kk = 0; kk < 4; kk++) { \
      const float* wr = wbase + (k4i * 4 + kk) * NH; \
      float4 wa  = *(const float4*)(wr + (tn << 2)); \
      float4 wb4 = *(const float4*)(wr + 256 + (tn << 2)); \
      float wv[8] = {wa.x, wa.y, wa.z, wa.w, wb4.x, wb4.y, wb4.z, wb4.w}; \
      _Pragma("unroll") \
      for (int r = 0; r < 4; r++) { \
        float hx = hb[r][kk]; \
        _Pragma("unroll") \
        for (int jj = 0; jj < 8; jj++) acc[r][jj] += hx * wv[jj]; \
      } \
    } \
  } }

    // initial prefetch: (t=0, chunk order index 0 -> chunk 0, kt=0)
    LDG_TILE(0, 0);

    for (int t = 0; t < NT; t++) {
#pragma unroll
        for (int ci = 0; ci < 4; ci++) {
            // gate chunk processing order: i(0), g(2), f(1), o(3)
            const int chunk = ((ci & 1) << 1) | (ci >> 1);

            float acc[4][8];
#pragma unroll
            for (int r = 0; r < 4; r++)
#pragma unroll
                for (int jj = 0; jj < 8; jj++) acc[r][jj] = 0.0f;

            for (int kt = 0; kt < 32; kt++) {
                const int buf = kt & 1;  // (t*128 + ci*32 + kt) & 1 == kt & 1
                STS_TILE(buf);
                int nkt = kt + 1, nci = ci;
                if (nkt == 32) { nkt = 0; nci = (ci + 1) & 3; }
                const int nchunk = ((nci & 1) << 1) | (nci >> 1);
                LDG_TILE(nchunk, nkt);   // prefetch next tile (wraps across step)
                __syncthreads();
                COMP_TILE(buf, kt);
                __syncthreads();
            }

            // epilogue: add x_proj, apply gate nonlinearity, update state
#pragma unroll
            for (int r = 0; r < 4; r++) {
                const float* xg = g_xproj + (size_t)(brow0 + r0 + r) * N4H + chunk * 512;
                float4 a = *(const float4*)(xg + (tn << 2));
                float4 b = *(const float4*)(xg + 256 + (tn << 2));
                float xv[8] = {a.x, a.y, a.z, a.w, b.x, b.y, b.z, b.w};
#pragma unroll
                for (int jj = 0; jj < 8; jj++) {
                    float v = acc[r][jj] + xv[jj];
                    if (chunk == 0)       ig[r][jj]  = sigf(v);                         // i
                    else if (chunk == 2)  ig[r][jj] *= tanhf(v);                        // * g
                    else if (chunk == 1)  cst[r][jj] = sigf(v) * cst[r][jj] + ig[r][jj];// c
                    else                  ig[r][jj]  = sigf(v) * tanhf(cst[r][jj]);     // h (o)
                }
            }

            if (chunk == 3) {
                // all reads of old h finished at the last tile's trailing barrier
#pragma unroll
                for (int r = 0; r < 4; r++) {
                    *(float4*)&h_sh[(r0 + r) * NH + (tn << 2)] =
                        make_float4(ig[r][0], ig[r][1], ig[r][2], ig[r][3]);
                    *(float4*)&h_sh[(r0 + r) * NH + 256 + (tn << 2)] =
                        make_float4(ig[r][4], ig[r][5], ig[r][6], ig[r][7]);
                }
                __syncthreads();
                // fused output projection: out[b, t, :] = h @ W_out.T + b_out
                if (tid < 128) {
                    float s0 = 0.f, s1 = 0.f, s2 = 0.f, s3 = 0.f;
                    const float* hp = h_sh + om * NH;
                    const float* wp = wout_sh + oa * 516;
#pragma unroll 8
                    for (int u4 = 0; u4 < 128; u4++) {
                        float4 hq = *(const float4*)(hp + (u4 << 2));
                        float4 wq = *(const float4*)(wp + (u4 << 2));
                        s0 += hq.x * wq.x; s1 += hq.y * wq.y;
                        s2 += hq.z * wq.z; s3 += hq.w * wq.w;
                    }
                    out[((brow0 + om) * NT + t) * NA + oa] = s0 + s1 + s2 + s3 + bo;
                }
            }
        }
    }
#undef LDG_TILE
#undef STS_TILE
#undef COMP_TILE
}

// ---------------------------------------------------------------------------
// Inputs (metadata order): z, W_ih, W_hh, b_ih, b_hh, W_out, b_out, seq_len
// ---------------------------------------------------------------------------
extern "C" void kernel_launch(void* const* d_in, const int* in_sizes, int n_in,
                              void* d_out, int out_size)
{
    (void)in_sizes; (void)n_in; (void)out_size;
    const float* z    = (const float*)d_in[0];
    const float* Wih  = (const float*)d_in[1];
    const float* Whh  = (const float*)d_in[2];
    const float* bih  = (const float*)d_in[3];
    const float* bhh  = (const float*)d_in[4];
    const float* Wout = (const float*)d_in[5];
    const float* bout = (const float*)d_in[6];
    float* out = (float*)d_out;

    xproj_kernel<<<dim3(N4H / 256, NB / 16), 256>>>(z, Wih, bih, bhh);

    const size_t smem_bytes = (size_t)(MR * NH + 2 * 16 * NH + NA * 516) * sizeof(float);
    cudaFuncSetAttribute(lstm_kernel, cudaFuncAttributeMaxDynamicSharedMemorySize,
                         (int)smem_bytes);
    lstm_kernel<<<NB / MR, TPB, smem_bytes>>>(Whh, Wout, bout, out);
}